// round 2
// baseline (speedup 1.0000x reference)
#include <cuda_runtime.h>

// TSM temporal shift: x (128, 96, 56, 56) f32, N_FRAME=8, fold=32.
//   c in [0,32):  out[b,t] = x[b,t+1]  (0 at t=7)
//   c in [32,64): out[b,t] = x[b,t-1]  (0 at t=0)
//   c in [64,96): out[b,t] = x[b,t]
// Pure HBM-bound permuted copy. float4-vectorized along hw.

static constexpr int HW4      = (56 * 56) / 4;   // 784 float4 per channel plane
static constexpr int C        = 96;
static constexpr int PER_BT4  = C * HW4;         // 75264 float4 per bt slice
static constexpr int BT       = 128;
static constexpr int TOTAL4   = BT * PER_BT4;    // 9,633,792 float4

__global__ __launch_bounds__(256) void tsm_kernel(const float4* __restrict__ in,
                                                  float4* __restrict__ out) {
    int i = blockIdx.x * 256 + threadIdx.x;

    int bt  = i / PER_BT4;
    int rem = i - bt * PER_BT4;
    int c   = rem / HW4;
    int t   = bt & 7;   // frame index within clip of 8

    int  src_bt;
    bool valid;
    if (c < 32) {            // shift left in time: take t+1
        valid  = (t < 7);
        src_bt = bt + 1;
    } else if (c < 64) {     // shift right in time: take t-1
        valid  = (t > 0);
        src_bt = bt - 1;
    } else {                 // passthrough
        valid  = true;
        src_bt = bt;
    }

    float4 v = make_float4(0.f, 0.f, 0.f, 0.f);
    if (valid) {
        v = in[src_bt * PER_BT4 + rem];
    }
    out[i] = v;
}

extern "C" void kernel_launch(void* const* d_in, const int* in_sizes, int n_in,
                              void* d_out, int out_size) {
    const float4* in  = (const float4*)d_in[0];
    float4*       out = (float4*)d_out;

    // TOTAL4 = 9,633,792 = 37,632 blocks * 256 threads exactly.
    tsm_kernel<<<TOTAL4 / 256, 256>>>(in, out);
}

// round 3
// speedup vs baseline: 1.0361x; 1.0361x over previous
#include <cuda_runtime.h>

// TSM temporal shift: x (128, 96, 56, 56) f32, N_FRAME=8, fold=32.
//   c in [0,32):  out[b,t] = x[b,t+1]  (0 at t=7)
//   c in [32,64): out[b,t] = x[b,t-1]  (0 at t=0)
//   c in [64,96): copy
// HBM-bound permuted copy.
// R2: 2D grid (bt on blockIdx.y) kills the /75264 divide; 3 front-batched
// LDG.128 per thread for MLP; __ldcs/__stcs streaming hints (no reuse,
// working set 2.4x L2).

static constexpr int HW4     = (56 * 56) / 4;  // 784 float4 per channel plane
static constexpr int C       = 96;
static constexpr int PER_BT4 = C * HW4;        // 75264 float4 per bt slice
static constexpr int V       = 3;              // float4 per thread
static constexpr int TPB     = 256;
static constexpr int BLK_X   = PER_BT4 / (V * TPB);  // 98, exact

__global__ __launch_bounds__(TPB) void tsm_kernel(const float4* __restrict__ in,
                                                  float4* __restrict__ out) {
    const int bt = blockIdx.y;
    const int t  = bt & 7;                     // frame within clip of 8

    const int base = blockIdx.x * (V * TPB) + threadIdx.x;

    const float4* src = in  + bt * PER_BT4;
    float4*       dst = out + bt * PER_BT4;

    int  rem[V];
    const float4* addr[V];
    bool valid[V];

    // Address generation for all V elements first (independent, back-to-back).
    #pragma unroll
    for (int k = 0; k < V; k++) {
        rem[k] = base + k * TPB;
        const int c = rem[k] / HW4;            // IMAD.HI magic divide
        int off;
        if (c < 32) {            // shift left in time: read t+1
            valid[k] = (t < 7);
            off = PER_BT4;
        } else if (c < 64) {     // shift right in time: read t-1
            valid[k] = (t > 0);
            off = -PER_BT4;
        } else {                 // passthrough
            valid[k] = true;
            off = 0;
        }
        addr[k] = src + off + rem[k];
    }

    // Front-batched loads (MLP=3), predicated on validity.
    float4 v[V];
    #pragma unroll
    for (int k = 0; k < V; k++) {
        v[k] = make_float4(0.f, 0.f, 0.f, 0.f);
        if (valid[k]) v[k] = __ldcs(addr[k]);
    }

    #pragma unroll
    for (int k = 0; k < V; k++) {
        __stcs(dst + rem[k], v[k]);
    }
}

extern "C" void kernel_launch(void* const* d_in, const int* in_sizes, int n_in,
                              void* d_out, int out_size) {
    const float4* in  = (const float4*)d_in[0];
    float4*       out = (float4*)d_out;

    dim3 grid(BLK_X, 128);   // (98, 128) — exact cover, no tail
    tsm_kernel<<<grid, TPB>>>(in, out);
}

// round 5
// speedup vs baseline: 1.0368x; 1.0007x over previous
#include <cuda_runtime.h>

// TSM temporal shift: x (128, 96, 56, 56) f32, N_FRAME=8, fold=32.
//   c in [0,32):  out[b,t] = x[b,t+1]  (0 at t=7)
//   c in [32,64): out[b,t] = x[b,t-1]  (0 at t=0)
//   c in [64,96): copy
// R3: block-uniform decomposition. Each channel group is a CONTIGUOUS
// 25088-float4 chunk per bt-slice, so map group->blockIdx.y, bt->blockIdx.z.
// All predication/offsets are blockIdx-uniform (no per-thread divides, zero
// blocks skip loads entirely), V=7 front-batched LDG.128 per thread (exact
// cover: 25088 = 14 * 256 * 7).

static constexpr int HW4     = (56 * 56) / 4;   // 784 float4 per channel plane
static constexpr int G4      = 32 * HW4;        // 25088 float4 per group per bt
static constexpr int PER_BT4 = 3 * G4;          // 75264 float4 per bt slice
static constexpr int V       = 7;               // float4 per thread
static constexpr int TPB     = 256;
static constexpr int BLK_X   = G4 / (V * TPB);  // 14, exact

__global__ __launch_bounds__(TPB) void tsm_kernel(const float4* __restrict__ in,
                                                  float4* __restrict__ out) {
    const int g  = blockIdx.y;       // channel group: 0 = t+1, 1 = t-1, 2 = copy
    const int bt = blockIdx.z;
    const int t  = bt & 7;           // frame within clip of 8

    // Block-uniform source shift and validity.
    const int  dt    = (g == 0) ? 1 : ((g == 1) ? -1 : 0);
    const bool valid = (g == 2) || ((g == 0) ? (t < 7) : (t > 0));

    const int chunk = g * G4 + blockIdx.x * (V * TPB) + threadIdx.x;
    const float4* src = in  + (bt + dt) * PER_BT4 + chunk;
    float4*       dst = out + bt * PER_BT4 + chunk;

    float4 v[V];
    if (valid) {
        // Front-batched loads: 7 independent LDG.128 in flight per thread.
        #pragma unroll
        for (int k = 0; k < V; k++) v[k] = __ldcs(src + k * TPB);
    } else {
        #pragma unroll
        for (int k = 0; k < V; k++) v[k] = make_float4(0.f, 0.f, 0.f, 0.f);
    }

    #pragma unroll
    for (int k = 0; k < V; k++) __stcs(dst + k * TPB, v[k]);
}

extern "C" void kernel_launch(void* const* d_in, const int* in_sizes, int n_in,
                              void* d_out, int out_size) {
    const float4* in  = (const float4*)d_in[0];
    float4*       out = (float4*)d_out;

    dim3 grid(BLK_X, 3, 128);   // (14, 3, 128) = 5376 blocks, exact cover
    tsm_kernel<<<grid, TPB>>>(in, out);
}